// round 1
// baseline (speedup 1.0000x reference)
#include <cuda_runtime.h>

#define Bsz   16
#define Lseq  2048
#define Hdim  512
#define N2    32
#define Tc    32
#define NC    (Lseq / Tc)   /* 64 chunks */
#define HG    8
#define USTRIDE 9           /* padded head-stride in smem: 9 coprime with 32 banks */

/* Precomputed mode-domain tables (module-scope device arrays; no runtime alloc) */
__device__ float2 g_P[Hdim][Tc][N2];   /* dtA^{T-1-t} * dtB            (layout [t][n]) */
__device__ float2 g_Q[Hdim][N2][Tc];   /* 2*C*dtA^{t+1}                (layout [n][t]) */
__device__ float2 g_AT[Hdim][N2];      /* dtA^T                                        */
__device__ float  g_K[Hdim][Tc];       /* K[h][j] = 2*Re(sum_n C*dtB*dtA^j)            */

__device__ __forceinline__ float2 cmul(float2 a, float2 b) {
    return make_float2(fmaf(a.x, b.x, -a.y * b.y), fmaf(a.x, b.y, a.y * b.x));
}

__global__ void s4d_precompute(const float* __restrict__ log_dt,
                               const float* __restrict__ B_re,
                               const float* __restrict__ B_im,
                               const float* __restrict__ Cmat,
                               const float* __restrict__ A_real,
                               const float* __restrict__ A_imag)
{
    int h = blockIdx.x;
    int n = threadIdx.x;            /* one mode per lane, 32 lanes */
    int idx = h * N2 + n;

    float dt  = expf(log_dt[h]);
    float Are = -expf(A_real[idx]) - 1e-6f;
    float Aim = A_imag[idx];

    /* bilinear: dtA = (1 + dt*A/2) / (1 + 1e-6 - dt*A/2); dtB = dt*B / denom */
    float2 num = make_float2(1.f + 0.5f * dt * Are, 0.5f * dt * Aim);
    float2 den = make_float2(1.f + 1e-6f - 0.5f * dt * Are, -0.5f * dt * Aim);
    float  inv = 1.f / (den.x * den.x + den.y * den.y);
    float2 dtA = make_float2((num.x * den.x + num.y * den.y) * inv,
                             (num.y * den.x - num.x * den.y) * inv);
    float2 Bc  = make_float2(dt * B_re[idx], dt * B_im[idx]);
    float2 dtB = make_float2((Bc.x * den.x + Bc.y * den.y) * inv,
                             (Bc.y * den.x - Bc.x * den.y) * inv);
    float  Cv  = Cmat[idx];

    /* P[t] = dtA^{T-1-t} * dtB  (built upward from t=T-1) */
    float2 p = dtB;
    for (int t = Tc - 1; t >= 0; --t) { g_P[h][t][n] = p; p = cmul(p, dtA); }

    /* Q[t] = 2*C*dtA^{t+1} (transposed layout [n][t] for conflict-free pass3 reads) */
    float2 q = make_float2(2.f * Cv * dtA.x, 2.f * Cv * dtA.y);
    for (int t = 0; t < Tc; ++t) { g_Q[h][n][t] = q; q = cmul(q, dtA); }

    /* dtA^32 via 5 squarings */
    float2 a = dtA;
    #pragma unroll
    for (int s = 0; s < 5; ++s) a = cmul(a, a);
    g_AT[h][n] = a;

    /* Toeplitz taps: K[j] = 2*Re(sum_n C*dtB*dtA^j) — warp reduce over modes */
    float2 ck = make_float2(Cv * dtB.x, Cv * dtB.y);
    for (int j = 0; j < Tc; ++j) {
        float v = ck.x;
        #pragma unroll
        for (int o = 16; o > 0; o >>= 1) v += __shfl_xor_sync(0xffffffffu, v, o);
        if (n == 0) g_K[h][j] = 2.f * v;
        ck = cmul(ck, dtA);
    }
}

/* smem plan (floats):
   u_s : Lseq*USTRIDE                    = 18432  (73728 B) -> reused as output staging
   ws  : NC*N2 float2                    =  2048 f2 (16384 B) -> chunk proj, then entry states
   Ps  : Tc*N2 float2                    =  1024 f2 ( 8192 B)
   Qs  : N2*Tc float2                    =  1024 f2 ( 8192 B)
   Ks  : Tc floats                       (128 B)
   total = 106624 B -> 2 CTAs/SM                                             */
#define SMEM_BYTES 106624

__global__ void __launch_bounds__(512, 2)
s4d_main(const float* __restrict__ u,
         const float* __restrict__ Dptr,
         float* __restrict__ out)
{
    extern __shared__ float sm[];
    float*  u_s = sm;
    float2* ws  = (float2*)(sm + Lseq * USTRIDE);
    float2* Ps  = ws + NC * N2;
    float2* Qs  = Ps + Tc * N2;
    float*  Ks  = (float*)(Qs + N2 * Tc);

    const int b    = blockIdx.y;
    const int h0   = blockIdx.x * HG;
    const int tid  = threadIdx.x;
    const int warp = tid >> 5;
    const int lane = tid & 31;
    const float Dv = *Dptr;

    /* ---- coalesced load of u[b, :, h0:h0+8] into padded smem ---- */
    const float* ub = u + (size_t)b * Lseq * Hdim + h0;
    for (int f = tid; f < Lseq * HG; f += 512) {
        int l = f >> 3, hh = f & 7;
        u_s[l * USTRIDE + hh] = ub[(size_t)l * Hdim + hh];
    }
    __syncthreads();

    const int cstep = 16 * Tc * USTRIDE;   /* smem stride between this warp's chunks */

    for (int hh = 0; hh < HG; ++hh) {
        const int h = h0 + hh;

        /* stage per-head tables */
        {
            const float2* gP = &g_P[h][0][0];
            const float2* gQ = &g_Q[h][0][0];
            Ps[tid] = gP[tid]; Ps[tid + 512] = gP[tid + 512];
            Qs[tid] = gQ[tid]; Qs[tid + 512] = gQ[tid + 512];
            if (tid < Tc) Ks[tid] = g_K[h][tid];
        }
        __syncthreads();

        /* ---- pass 1: chunk projections w_c[n] = sum_t P[t][n]*u[cT+t] ----
           warp handles chunks {warp, warp+16, warp+32, warp+48}; lane = mode n */
        {
            const int n = lane;
            float w0r = 0, w0i = 0, w1r = 0, w1i = 0;
            float w2r = 0, w2i = 0, w3r = 0, w3i = 0;
            const int base0 = (warp * Tc) * USTRIDE + hh;
            #pragma unroll 8
            for (int t = 0; t < Tc; ++t) {
                float2 p  = Ps[t * N2 + n];
                int    a  = base0 + t * USTRIDE;
                float  u0 = u_s[a];
                float  u1 = u_s[a + cstep];
                float  u2 = u_s[a + 2 * cstep];
                float  u3 = u_s[a + 3 * cstep];
                w0r = fmaf(p.x, u0, w0r); w0i = fmaf(p.y, u0, w0i);
                w1r = fmaf(p.x, u1, w1r); w1i = fmaf(p.y, u1, w1i);
                w2r = fmaf(p.x, u2, w2r); w2i = fmaf(p.y, u2, w2i);
                w3r = fmaf(p.x, u3, w3r); w3i = fmaf(p.y, u3, w3i);
            }
            ws[(warp     ) * N2 + n] = make_float2(w0r, w0i);
            ws[(warp + 16) * N2 + n] = make_float2(w1r, w1i);
            ws[(warp + 32) * N2 + n] = make_float2(w2r, w2i);
            ws[(warp + 48) * N2 + n] = make_float2(w3r, w3i);
        }
        __syncthreads();

        /* ---- pass 2: sequential scan over chunks (warp 0, lane = mode) ----
           in-place: ws[c] becomes the state ENTERING chunk c */
        if (warp == 0) {
            const int n = lane;
            float2 AT = g_AT[h][n];
            float xr = 0.f, xi = 0.f;
            #pragma unroll 8
            for (int c = 0; c < NC; ++c) {
                float2 wv = ws[c * N2 + n];
                ws[c * N2 + n] = make_float2(xr, xi);
                float nr = fmaf(AT.x, xr, fmaf(-AT.y, xi, wv.x));
                float ni = fmaf(AT.x, xi, fmaf( AT.y, xr, wv.y));
                xr = nr; xi = ni;
            }
        }
        __syncthreads();

        /* ---- pass 3: outputs. lane = local timestep t, 4 chunks per warp ---- */
        {
            const int t = lane;
            float y0 = 0, y1 = 0, y2 = 0, y3 = 0;

            /* inter-chunk correction: Re( Q[t][n] * x_entry[c][n] ) */
            #pragma unroll 8
            for (int n = 0; n < N2; ++n) {
                float2 q  = Qs[n * Tc + t];
                float2 s0 = ws[(warp     ) * N2 + n];
                float2 s1 = ws[(warp + 16) * N2 + n];
                float2 s2 = ws[(warp + 32) * N2 + n];
                float2 s3 = ws[(warp + 48) * N2 + n];
                y0 = fmaf(q.x, s0.x, fmaf(-q.y, s0.y, y0));
                y1 = fmaf(q.x, s1.x, fmaf(-q.y, s1.y, y1));
                y2 = fmaf(q.x, s2.x, fmaf(-q.y, s2.y, y2));
                y3 = fmaf(q.x, s3.x, fmaf(-q.y, s3.y, y3));
            }

            /* intra-chunk Toeplitz: sum_{j<=t} K[j]*u[cT+t-j] */
            const int base0 = (warp * Tc) * USTRIDE + hh;
            #pragma unroll 8
            for (int j = 0; j < Tc; ++j) {
                float kj  = (j <= t) ? Ks[j] : 0.f;
                int   ix  = t - j; ix = ix < 0 ? 0 : ix;
                int   a   = base0 + ix * USTRIDE;
                y0 = fmaf(kj, u_s[a            ], y0);
                y1 = fmaf(kj, u_s[a +     cstep], y1);
                y2 = fmaf(kj, u_s[a + 2 * cstep], y2);
                y3 = fmaf(kj, u_s[a + 3 * cstep], y3);
            }

            /* + D*u, exact GELU, write back in place over u column hh */
            const int a0 = base0 + t * USTRIDE;
            float uu0 = u_s[a0], uu1 = u_s[a0 + cstep];
            float uu2 = u_s[a0 + 2 * cstep], uu3 = u_s[a0 + 3 * cstep];
            y0 = fmaf(Dv, uu0, y0); y1 = fmaf(Dv, uu1, y1);
            y2 = fmaf(Dv, uu2, y2); y3 = fmaf(Dv, uu3, y3);
            const float is2 = 0.70710678118654752440f;
            y0 = 0.5f * y0 * (1.f + erff(y0 * is2));
            y1 = 0.5f * y1 * (1.f + erff(y1 * is2));
            y2 = 0.5f * y2 * (1.f + erff(y2 * is2));
            y3 = 0.5f * y3 * (1.f + erff(y3 * is2));
            __syncwarp();   /* all reads of this chunk's u done before overwrite */
            u_s[a0            ] = y0;
            u_s[a0 +     cstep] = y1;
            u_s[a0 + 2 * cstep] = y2;
            u_s[a0 + 3 * cstep] = y3;
        }
        __syncthreads();   /* protect tables + ws before next head */
    }

    /* ---- coalesced store ---- */
    float* ob = out + (size_t)b * Lseq * Hdim + h0;
    for (int f = tid; f < Lseq * HG; f += 512) {
        int l = f >> 3, hh = f & 7;
        ob[(size_t)l * Hdim + hh] = u_s[l * USTRIDE + hh];
    }
}

extern "C" void kernel_launch(void* const* d_in, const int* in_sizes, int n_in,
                              void* d_out, int out_size)
{
    const float* u      = (const float*)d_in[0];
    const float* log_dt = (const float*)d_in[1];
    const float* B_re   = (const float*)d_in[2];
    const float* B_im   = (const float*)d_in[3];
    const float* C      = (const float*)d_in[4];
    const float* A_real = (const float*)d_in[5];
    const float* A_imag = (const float*)d_in[6];
    const float* D      = (const float*)d_in[7];
    float* out = (float*)d_out;

    cudaFuncSetAttribute(s4d_main, cudaFuncAttributeMaxDynamicSharedMemorySize,
                         SMEM_BYTES);

    s4d_precompute<<<Hdim, N2>>>(log_dt, B_re, B_im, C, A_real, A_imag);

    dim3 grid(Hdim / HG, Bsz);
    s4d_main<<<grid, 512, SMEM_BYTES>>>(u, D, out);
}

// round 2
// speedup vs baseline: 1.0002x; 1.0002x over previous
#include <cuda_runtime.h>

#define Bsz   16
#define Lseq  2048
#define Hdim  512
#define N2    32
#define Tc    32
#define NC    (Lseq / Tc)   /* 64 chunks */
#define HG    8
#define USTRIDE 9           /* padded head-stride in smem: 9 coprime with 32 banks */

/* Precomputed mode-domain tables (module-scope device arrays; no runtime alloc) */
__device__ float2 g_P[Hdim][Tc][N2];   /* dtA^{T-1-t} * dtB            (layout [t][n]) */
__device__ float2 g_Q[Hdim][N2][Tc];   /* 2*C*dtA^{t+1}                (layout [n][t]) */
__device__ float2 g_AT[Hdim][N2];      /* dtA^T                                        */
__device__ float  g_K[Hdim][Tc];       /* K[h][j] = 2*Re(sum_n C*dtB*dtA^j)            */

__device__ __forceinline__ float2 cmul(float2 a, float2 b) {
    return make_float2(fmaf(a.x, b.x, -a.y * b.y), fmaf(a.x, b.y, a.y * b.x));
}

__global__ void s4d_precompute(const float* __restrict__ log_dt,
                               const float* __restrict__ B_re,
                               const float* __restrict__ B_im,
                               const float* __restrict__ Cmat,
                               const float* __restrict__ A_real,
                               const float* __restrict__ A_imag)
{
    int h = blockIdx.x;
    int n = threadIdx.x;            /* one mode per lane, 32 lanes */
    int idx = h * N2 + n;

    float dt  = expf(log_dt[h]);
    float Are = -expf(A_real[idx]) - 1e-6f;
    float Aim = A_imag[idx];

    /* bilinear: dtA = (1 + dt*A/2) / (1 + 1e-6 - dt*A/2); dtB = dt*B / denom */
    float2 num = make_float2(1.f + 0.5f * dt * Are, 0.5f * dt * Aim);
    float2 den = make_float2(1.f + 1e-6f - 0.5f * dt * Are, -0.5f * dt * Aim);
    float  inv = 1.f / (den.x * den.x + den.y * den.y);
    float2 dtA = make_float2((num.x * den.x + num.y * den.y) * inv,
                             (num.y * den.x - num.x * den.y) * inv);
    float2 Bc  = make_float2(dt * B_re[idx], dt * B_im[idx]);
    float2 dtB = make_float2((Bc.x * den.x + Bc.y * den.y) * inv,
                             (Bc.y * den.x - Bc.x * den.y) * inv);
    float  Cv  = Cmat[idx];

    /* P[t] = dtA^{T-1-t} * dtB  (built upward from t=T-1) */
    float2 p = dtB;
    for (int t = Tc - 1; t >= 0; --t) { g_P[h][t][n] = p; p = cmul(p, dtA); }

    /* Q[t] = 2*C*dtA^{t+1} (transposed layout [n][t] for conflict-free pass3 reads) */
    float2 q = make_float2(2.f * Cv * dtA.x, 2.f * Cv * dtA.y);
    for (int t = 0; t < Tc; ++t) { g_Q[h][n][t] = q; q = cmul(q, dtA); }

    /* dtA^32 via 5 squarings */
    float2 a = dtA;
    #pragma unroll
    for (int s = 0; s < 5; ++s) a = cmul(a, a);
    g_AT[h][n] = a;

    /* Toeplitz taps: K[j] = 2*Re(sum_n C*dtB*dtA^j) — warp reduce over modes */
    float2 ck = make_float2(Cv * dtB.x, Cv * dtB.y);
    for (int j = 0; j < Tc; ++j) {
        float v = ck.x;
        #pragma unroll
        for (int o = 16; o > 0; o >>= 1) v += __shfl_xor_sync(0xffffffffu, v, o);
        if (n == 0) g_K[h][j] = 2.f * v;
        ck = cmul(ck, dtA);
    }
}

/* smem plan (floats):
   u_s : Lseq*USTRIDE                    = 18432  (73728 B) -> reused as output staging
   ws  : NC*N2 float2                    =  2048 f2 (16384 B) -> chunk proj, then entry states
   Ps  : Tc*N2 float2                    =  1024 f2 ( 8192 B)
   Qs  : N2*Tc float2                    =  1024 f2 ( 8192 B)
   Ks  : Tc floats                       (128 B)
   total = 106624 B -> 2 CTAs/SM                                             */
#define SMEM_BYTES 106624

__global__ void __launch_bounds__(512, 2)
s4d_main(const float* __restrict__ u,
         const float* __restrict__ Dptr,
         float* __restrict__ out)
{
    extern __shared__ float sm[];
    float*  u_s = sm;
    float2* ws  = (float2*)(sm + Lseq * USTRIDE);
    float2* Ps  = ws + NC * N2;
    float2* Qs  = Ps + Tc * N2;
    float*  Ks  = (float*)(Qs + N2 * Tc);

    const int b    = blockIdx.y;
    const int h0   = blockIdx.x * HG;
    const int tid  = threadIdx.x;
    const int warp = tid >> 5;
    const int lane = tid & 31;
    const float Dv = *Dptr;

    /* ---- coalesced load of u[b, :, h0:h0+8] into padded smem ---- */
    const float* ub = u + (size_t)b * Lseq * Hdim + h0;
    for (int f = tid; f < Lseq * HG; f += 512) {
        int l = f >> 3, hh = f & 7;
        u_s[l * USTRIDE + hh] = ub[(size_t)l * Hdim + hh];
    }
    __syncthreads();

    const int cstep = 16 * Tc * USTRIDE;   /* smem stride between this warp's chunks */

    for (int hh = 0; hh < HG; ++hh) {
        const int h = h0 + hh;

        /* stage per-head tables */
        {
            const float2* gP = &g_P[h][0][0];
            const float2* gQ = &g_Q[h][0][0];
            Ps[tid] = gP[tid]; Ps[tid + 512] = gP[tid + 512];
            Qs[tid] = gQ[tid]; Qs[tid + 512] = gQ[tid + 512];
            if (tid < Tc) Ks[tid] = g_K[h][tid];
        }
        __syncthreads();

        /* ---- pass 1: chunk projections w_c[n] = sum_t P[t][n]*u[cT+t] ----
           warp handles chunks {warp, warp+16, warp+32, warp+48}; lane = mode n */
        {
            const int n = lane;
            float w0r = 0, w0i = 0, w1r = 0, w1i = 0;
            float w2r = 0, w2i = 0, w3r = 0, w3i = 0;
            const int base0 = (warp * Tc) * USTRIDE + hh;
            #pragma unroll 8
            for (int t = 0; t < Tc; ++t) {
                float2 p  = Ps[t * N2 + n];
                int    a  = base0 + t * USTRIDE;
                float  u0 = u_s[a];
                float  u1 = u_s[a + cstep];
                float  u2 = u_s[a + 2 * cstep];
                float  u3 = u_s[a + 3 * cstep];
                w0r = fmaf(p.x, u0, w0r); w0i = fmaf(p.y, u0, w0i);
                w1r = fmaf(p.x, u1, w1r); w1i = fmaf(p.y, u1, w1i);
                w2r = fmaf(p.x, u2, w2r); w2i = fmaf(p.y, u2, w2i);
                w3r = fmaf(p.x, u3, w3r); w3i = fmaf(p.y, u3, w3i);
            }
            ws[(warp     ) * N2 + n] = make_float2(w0r, w0i);
            ws[(warp + 16) * N2 + n] = make_float2(w1r, w1i);
            ws[(warp + 32) * N2 + n] = make_float2(w2r, w2i);
            ws[(warp + 48) * N2 + n] = make_float2(w3r, w3i);
        }
        __syncthreads();

        /* ---- pass 2: sequential scan over chunks (warp 0, lane = mode) ----
           in-place: ws[c] becomes the state ENTERING chunk c */
        if (warp == 0) {
            const int n = lane;
            float2 AT = g_AT[h][n];
            float xr = 0.f, xi = 0.f;
            #pragma unroll 8
            for (int c = 0; c < NC; ++c) {
                float2 wv = ws[c * N2 + n];
                ws[c * N2 + n] = make_float2(xr, xi);
                float nr = fmaf(AT.x, xr, fmaf(-AT.y, xi, wv.x));
                float ni = fmaf(AT.x, xi, fmaf( AT.y, xr, wv.y));
                xr = nr; xi = ni;
            }
        }
        __syncthreads();

        /* ---- pass 3: outputs. lane = local timestep t, 4 chunks per warp ---- */
        {
            const int t = lane;
            float y0 = 0, y1 = 0, y2 = 0, y3 = 0;

            /* inter-chunk correction: Re( Q[t][n] * x_entry[c][n] ) */
            #pragma unroll 8
            for (int n = 0; n < N2; ++n) {
                float2 q  = Qs[n * Tc + t];
                float2 s0 = ws[(warp     ) * N2 + n];
                float2 s1 = ws[(warp + 16) * N2 + n];
                float2 s2 = ws[(warp + 32) * N2 + n];
                float2 s3 = ws[(warp + 48) * N2 + n];
                y0 = fmaf(q.x, s0.x, fmaf(-q.y, s0.y, y0));
                y1 = fmaf(q.x, s1.x, fmaf(-q.y, s1.y, y1));
                y2 = fmaf(q.x, s2.x, fmaf(-q.y, s2.y, y2));
                y3 = fmaf(q.x, s3.x, fmaf(-q.y, s3.y, y3));
            }

            /* intra-chunk Toeplitz: sum_{j<=t} K[j]*u[cT+t-j] */
            const int base0 = (warp * Tc) * USTRIDE + hh;
            #pragma unroll 8
            for (int j = 0; j < Tc; ++j) {
                float kj  = (j <= t) ? Ks[j] : 0.f;
                int   ix  = t - j; ix = ix < 0 ? 0 : ix;
                int   a   = base0 + ix * USTRIDE;
                y0 = fmaf(kj, u_s[a            ], y0);
                y1 = fmaf(kj, u_s[a +     cstep], y1);
                y2 = fmaf(kj, u_s[a + 2 * cstep], y2);
                y3 = fmaf(kj, u_s[a + 3 * cstep], y3);
            }

            /* + D*u, exact GELU, write back in place over u column hh */
            const int a0 = base0 + t * USTRIDE;
            float uu0 = u_s[a0], uu1 = u_s[a0 + cstep];
            float uu2 = u_s[a0 + 2 * cstep], uu3 = u_s[a0 + 3 * cstep];
            y0 = fmaf(Dv, uu0, y0); y1 = fmaf(Dv, uu1, y1);
            y2 = fmaf(Dv, uu2, y2); y3 = fmaf(Dv, uu3, y3);
            const float is2 = 0.70710678118654752440f;
            y0 = 0.5f * y0 * (1.f + erff(y0 * is2));
            y1 = 0.5f * y1 * (1.f + erff(y1 * is2));
            y2 = 0.5f * y2 * (1.f + erff(y2 * is2));
            y3 = 0.5f * y3 * (1.f + erff(y3 * is2));
            __syncwarp();   /* all reads of this chunk's u done before overwrite */
            u_s[a0            ] = y0;
            u_s[a0 +     cstep] = y1;
            u_s[a0 + 2 * cstep] = y2;
            u_s[a0 + 3 * cstep] = y3;
        }
        __syncthreads();   /* protect tables + ws before next head */
    }

    /* ---- coalesced store ---- */
    float* ob = out + (size_t)b * Lseq * Hdim + h0;
    for (int f = tid; f < Lseq * HG; f += 512) {
        int l = f >> 3, hh = f & 7;
        ob[(size_t)l * Hdim + hh] = u_s[l * USTRIDE + hh];
    }
}

extern "C" void kernel_launch(void* const* d_in, const int* in_sizes, int n_in,
                              void* d_out, int out_size)
{
    const float* u      = (const float*)d_in[0];
    const float* log_dt = (const float*)d_in[1];
    const float* B_re   = (const float*)d_in[2];
    const float* B_im   = (const float*)d_in[3];
    const float* C      = (const float*)d_in[4];
    const float* A_real = (const float*)d_in[5];
    const float* A_imag = (const float*)d_in[6];
    const float* D      = (const float*)d_in[7];
    float* out = (float*)d_out;

    cudaFuncSetAttribute(s4d_main, cudaFuncAttributeMaxDynamicSharedMemorySize,
                         SMEM_BYTES);

    s4d_precompute<<<Hdim, N2>>>(log_dt, B_re, B_im, C, A_real, A_imag);

    dim3 grid(Hdim / HG, Bsz);
    s4d_main<<<grid, 512, SMEM_BYTES>>>(u, D, out);
}

// round 3
// speedup vs baseline: 1.0011x; 1.0009x over previous
#include <cuda_runtime.h>

#define Bsz   16
#define Lseq  2048
#define Hdim  512
#define N2    32
#define Tc    32
#define NC    (Lseq / Tc)   /* 64 chunks */
#define HG    8
#define USTRIDE 9           /* padded head-stride in smem: 9 coprime with 32 banks */

/* Precomputed mode-domain tables (module-scope device arrays; no runtime alloc) */
__device__ float2 g_P[Hdim][Tc][N2];   /* dtA^{T-1-t} * dtB            (layout [t][n]) */
__device__ float2 g_Q[Hdim][N2][Tc];   /* 2*C*dtA^{t+1}                (layout [n][t]) */
__device__ float2 g_AT[Hdim][N2];      /* dtA^T                                        */
__device__ float  g_K[Hdim][Tc];       /* K[h][j] = 2*Re(sum_n C*dtB*dtA^j)            */

__device__ __forceinline__ float2 cmul(float2 a, float2 b) {
    return make_float2(fmaf(a.x, b.x, -a.y * b.y), fmaf(a.x, b.y, a.y * b.x));
}

__global__ void s4d_precompute(const float* __restrict__ log_dt,
                               const float* __restrict__ B_re,
                               const float* __restrict__ B_im,
                               const float* __restrict__ Cmat,
                               const float* __restrict__ A_real,
                               const float* __restrict__ A_imag)
{
    int h = blockIdx.x;
    int n = threadIdx.x;            /* one mode per lane, 32 lanes */
    int idx = h * N2 + n;

    float dt  = expf(log_dt[h]);
    float Are = -expf(A_real[idx]) - 1e-6f;
    float Aim = A_imag[idx];

    /* bilinear: dtA = (1 + dt*A/2) / (1 + 1e-6 - dt*A/2); dtB = dt*B / denom */
    float2 num = make_float2(1.f + 0.5f * dt * Are, 0.5f * dt * Aim);
    float2 den = make_float2(1.f + 1e-6f - 0.5f * dt * Are, -0.5f * dt * Aim);
    float  inv = 1.f / (den.x * den.x + den.y * den.y);
    float2 dtA = make_float2((num.x * den.x + num.y * den.y) * inv,
                             (num.y * den.x - num.x * den.y) * inv);
    float2 Bc  = make_float2(dt * B_re[idx], dt * B_im[idx]);
    float2 dtB = make_float2((Bc.x * den.x + Bc.y * den.y) * inv,
                             (Bc.y * den.x - Bc.x * den.y) * inv);
    float  Cv  = Cmat[idx];

    /* P[t] = dtA^{T-1-t} * dtB  (built upward from t=T-1) */
    float2 p = dtB;
    for (int t = Tc - 1; t >= 0; --t) { g_P[h][t][n] = p; p = cmul(p, dtA); }

    /* Q[t] = 2*C*dtA^{t+1} (transposed layout [n][t] for conflict-free pass3 reads) */
    float2 q = make_float2(2.f * Cv * dtA.x, 2.f * Cv * dtA.y);
    for (int t = 0; t < Tc; ++t) { g_Q[h][n][t] = q; q = cmul(q, dtA); }

    /* dtA^32 via 5 squarings */
    float2 a = dtA;
    #pragma unroll
    for (int s = 0; s < 5; ++s) a = cmul(a, a);
    g_AT[h][n] = a;

    /* Toeplitz taps: K[j] = 2*Re(sum_n C*dtB*dtA^j) — warp reduce over modes */
    float2 ck = make_float2(Cv * dtB.x, Cv * dtB.y);
    for (int j = 0; j < Tc; ++j) {
        float v = ck.x;
        #pragma unroll
        for (int o = 16; o > 0; o >>= 1) v += __shfl_xor_sync(0xffffffffu, v, o);
        if (n == 0) g_K[h][j] = 2.f * v;
        ck = cmul(ck, dtA);
    }
}

/* smem plan (floats):
   u_s : Lseq*USTRIDE                    = 18432  (73728 B) -> reused as output staging
   ws  : NC*N2 float2                    =  2048 f2 (16384 B) -> chunk proj, then entry states
   Ps  : Tc*N2 float2                    =  1024 f2 ( 8192 B)
   Qs  : N2*Tc float2                    =  1024 f2 ( 8192 B)
   Ks  : Tc floats                       (128 B)
   total = 106624 B -> 2 CTAs/SM                                             */
#define SMEM_BYTES 106624

__global__ void __launch_bounds__(512, 2)
s4d_main(const float* __restrict__ u,
         const float* __restrict__ Dptr,
         float* __restrict__ out)
{
    extern __shared__ float sm[];
    float*  u_s = sm;
    float2* ws  = (float2*)(sm + Lseq * USTRIDE);
    float2* Ps  = ws + NC * N2;
    float2* Qs  = Ps + Tc * N2;
    float*  Ks  = (float*)(Qs + N2 * Tc);

    const int b    = blockIdx.y;
    const int h0   = blockIdx.x * HG;
    const int tid  = threadIdx.x;
    const int warp = tid >> 5;
    const int lane = tid & 31;
    const float Dv = *Dptr;

    /* ---- coalesced load of u[b, :, h0:h0+8] into padded smem ---- */
    const float* ub = u + (size_t)b * Lseq * Hdim + h0;
    for (int f = tid; f < Lseq * HG; f += 512) {
        int l = f >> 3, hh = f & 7;
        u_s[l * USTRIDE + hh] = ub[(size_t)l * Hdim + hh];
    }
    __syncthreads();

    const int cstep = 16 * Tc * USTRIDE;   /* smem stride between this warp's chunks */

    for (int hh = 0; hh < HG; ++hh) {
        const int h = h0 + hh;

        /* stage per-head tables */
        {
            const float2* gP = &g_P[h][0][0];
            const float2* gQ = &g_Q[h][0][0];
            Ps[tid] = gP[tid]; Ps[tid + 512] = gP[tid + 512];
            Qs[tid] = gQ[tid]; Qs[tid + 512] = gQ[tid + 512];
            if (tid < Tc) Ks[tid] = g_K[h][tid];
        }
        __syncthreads();

        /* ---- pass 1: chunk projections w_c[n] = sum_t P[t][n]*u[cT+t] ----
           warp handles chunks {warp, warp+16, warp+32, warp+48}; lane = mode n */
        {
            const int n = lane;
            float w0r = 0, w0i = 0, w1r = 0, w1i = 0;
            float w2r = 0, w2i = 0, w3r = 0, w3i = 0;
            const int base0 = (warp * Tc) * USTRIDE + hh;
            #pragma unroll 8
            for (int t = 0; t < Tc; ++t) {
                float2 p  = Ps[t * N2 + n];
                int    a  = base0 + t * USTRIDE;
                float  u0 = u_s[a];
                float  u1 = u_s[a + cstep];
                float  u2 = u_s[a + 2 * cstep];
                float  u3 = u_s[a + 3 * cstep];
                w0r = fmaf(p.x, u0, w0r); w0i = fmaf(p.y, u0, w0i);
                w1r = fmaf(p.x, u1, w1r); w1i = fmaf(p.y, u1, w1i);
                w2r = fmaf(p.x, u2, w2r); w2i = fmaf(p.y, u2, w2i);
                w3r = fmaf(p.x, u3, w3r); w3i = fmaf(p.y, u3, w3i);
            }
            ws[(warp     ) * N2 + n] = make_float2(w0r, w0i);
            ws[(warp + 16) * N2 + n] = make_float2(w1r, w1i);
            ws[(warp + 32) * N2 + n] = make_float2(w2r, w2i);
            ws[(warp + 48) * N2 + n] = make_float2(w3r, w3i);
        }
        __syncthreads();

        /* ---- pass 2: sequential scan over chunks (warp 0, lane = mode) ----
           in-place: ws[c] becomes the state ENTERING chunk c */
        if (warp == 0) {
            const int n = lane;
            float2 AT = g_AT[h][n];
            float xr = 0.f, xi = 0.f;
            #pragma unroll 8
            for (int c = 0; c < NC; ++c) {
                float2 wv = ws[c * N2 + n];
                ws[c * N2 + n] = make_float2(xr, xi);
                float nr = fmaf(AT.x, xr, fmaf(-AT.y, xi, wv.x));
                float ni = fmaf(AT.x, xi, fmaf( AT.y, xr, wv.y));
                xr = nr; xi = ni;
            }
        }
        __syncthreads();

        /* ---- pass 3: outputs. lane = local timestep t, 4 chunks per warp ---- */
        {
            const int t = lane;
            float y0 = 0, y1 = 0, y2 = 0, y3 = 0;

            /* inter-chunk correction: Re( Q[t][n] * x_entry[c][n] ) */
            #pragma unroll 8
            for (int n = 0; n < N2; ++n) {
                float2 q  = Qs[n * Tc + t];
                float2 s0 = ws[(warp     ) * N2 + n];
                float2 s1 = ws[(warp + 16) * N2 + n];
                float2 s2 = ws[(warp + 32) * N2 + n];
                float2 s3 = ws[(warp + 48) * N2 + n];
                y0 = fmaf(q.x, s0.x, fmaf(-q.y, s0.y, y0));
                y1 = fmaf(q.x, s1.x, fmaf(-q.y, s1.y, y1));
                y2 = fmaf(q.x, s2.x, fmaf(-q.y, s2.y, y2));
                y3 = fmaf(q.x, s3.x, fmaf(-q.y, s3.y, y3));
            }

            /* intra-chunk Toeplitz: sum_{j<=t} K[j]*u[cT+t-j] */
            const int base0 = (warp * Tc) * USTRIDE + hh;
            #pragma unroll 8
            for (int j = 0; j < Tc; ++j) {
                float kj  = (j <= t) ? Ks[j] : 0.f;
                int   ix  = t - j; ix = ix < 0 ? 0 : ix;
                int   a   = base0 + ix * USTRIDE;
                y0 = fmaf(kj, u_s[a            ], y0);
                y1 = fmaf(kj, u_s[a +     cstep], y1);
                y2 = fmaf(kj, u_s[a + 2 * cstep], y2);
                y3 = fmaf(kj, u_s[a + 3 * cstep], y3);
            }

            /* + D*u, exact GELU, write back in place over u column hh */
            const int a0 = base0 + t * USTRIDE;
            float uu0 = u_s[a0], uu1 = u_s[a0 + cstep];
            float uu2 = u_s[a0 + 2 * cstep], uu3 = u_s[a0 + 3 * cstep];
            y0 = fmaf(Dv, uu0, y0); y1 = fmaf(Dv, uu1, y1);
            y2 = fmaf(Dv, uu2, y2); y3 = fmaf(Dv, uu3, y3);
            const float is2 = 0.70710678118654752440f;
            y0 = 0.5f * y0 * (1.f + erff(y0 * is2));
            y1 = 0.5f * y1 * (1.f + erff(y1 * is2));
            y2 = 0.5f * y2 * (1.f + erff(y2 * is2));
            y3 = 0.5f * y3 * (1.f + erff(y3 * is2));
            __syncwarp();   /* all reads of this chunk's u done before overwrite */
            u_s[a0            ] = y0;
            u_s[a0 +     cstep] = y1;
            u_s[a0 + 2 * cstep] = y2;
            u_s[a0 + 3 * cstep] = y3;
        }
        __syncthreads();   /* protect tables + ws before next head */
    }

    /* ---- coalesced store ---- */
    float* ob = out + (size_t)b * Lseq * Hdim + h0;
    for (int f = tid; f < Lseq * HG; f += 512) {
        int l = f >> 3, hh = f & 7;
        ob[(size_t)l * Hdim + hh] = u_s[l * USTRIDE + hh];
    }
}

extern "C" void kernel_launch(void* const* d_in, const int* in_sizes, int n_in,
                              void* d_out, int out_size)
{
    const float* u      = (const float*)d_in[0];
    const float* log_dt = (const float*)d_in[1];
    const float* B_re   = (const float*)d_in[2];
    const float* B_im   = (const float*)d_in[3];
    const float* C      = (const float*)d_in[4];
    const float* A_real = (const float*)d_in[5];
    const float* A_imag = (const float*)d_in[6];
    const float* D      = (const float*)d_in[7];
    float* out = (float*)d_out;

    cudaFuncSetAttribute(s4d_main, cudaFuncAttributeMaxDynamicSharedMemorySize,
                         SMEM_BYTES);

    s4d_precompute<<<Hdim, N2>>>(log_dt, B_re, B_im, C, A_real, A_imag);

    dim3 grid(Hdim / HG, Bsz);
    s4d_main<<<grid, 512, SMEM_BYTES>>>(u, D, out);
}

// round 4
// speedup vs baseline: 1.0493x; 1.0481x over previous
#include <cuda_runtime.h>

#define Bsz   16
#define Lseq  2048
#define Hdim  512
#define N2    32
#define Tc    32
#define NC    (Lseq / Tc)   /* 64 chunks */
#define HG    8
#define LPAD  2052          /* per-head time-contiguous stride (mult of 4, CF with hh*4+l) */

/* ---- precomputed per-mode tables (module-scope; no runtime alloc) ---- */
__device__ float4 g_AB[Hdim][N2];        /* (dtA.re, dtA.im, dtB.re, dtB.im)       */
__device__ float2 g_Q0[Hdim][N2];        /* 2*C*dtA                                */
__device__ float2 g_AT[Hdim][N2];        /* dtA^32                                 */
__device__ float  g_Vr[Hdim][N2][Tc];    /* Re(dtA^t)                              */
__device__ float  g_Vin[Hdim][N2][Tc];   /* -Im(dtA^t)  (negated for FMA folding)  */
__device__ float  g_K[Hdim][Tc];         /* K[j] = 2*Re(sum_n C*dtB*dtA^j)         */

__device__ __forceinline__ float2 cmul(float2 a, float2 b) {
    return make_float2(fmaf(a.x, b.x, -a.y * b.y), fmaf(a.x, b.y, a.y * b.x));
}

__global__ void s4d_precompute(const float* __restrict__ log_dt,
                               const float* __restrict__ B_re,
                               const float* __restrict__ B_im,
                               const float* __restrict__ Cmat,
                               const float* __restrict__ A_real,
                               const float* __restrict__ A_imag)
{
    int h = blockIdx.x;
    int n = threadIdx.x;
    int idx = h * N2 + n;

    float dt  = expf(log_dt[h]);
    float Are = -expf(A_real[idx]) - 1e-6f;
    float Aim = A_imag[idx];

    float2 num = make_float2(1.f + 0.5f * dt * Are, 0.5f * dt * Aim);
    float2 den = make_float2(1.f + 1e-6f - 0.5f * dt * Are, -0.5f * dt * Aim);
    float  inv = 1.f / (den.x * den.x + den.y * den.y);
    float2 dtA = make_float2((num.x * den.x + num.y * den.y) * inv,
                             (num.y * den.x - num.x * den.y) * inv);
    float2 Bc  = make_float2(dt * B_re[idx], dt * B_im[idx]);
    float2 dtB = make_float2((Bc.x * den.x + Bc.y * den.y) * inv,
                             (Bc.y * den.x - Bc.x * den.y) * inv);
    float  Cv  = Cmat[idx];

    g_AB[h][n] = make_float4(dtA.x, dtA.y, dtB.x, dtB.y);
    g_Q0[h][n] = make_float2(2.f * Cv * dtA.x, 2.f * Cv * dtA.y);

    /* dtA^32 via 5 squarings */
    float2 a = dtA;
    #pragma unroll
    for (int s = 0; s < 5; ++s) a = cmul(a, a);
    g_AT[h][n] = a;

    /* Vandermonde planes: v = dtA^t, t = 0..31 */
    float2 v = make_float2(1.f, 0.f);
    for (int t = 0; t < Tc; ++t) {
        g_Vr [h][n][t] =  v.x;
        g_Vin[h][n][t] = -v.y;
        v = cmul(v, dtA);
    }

    /* Toeplitz taps */
    float2 ck = make_float2(Cv * dtB.x, Cv * dtB.y);
    for (int j = 0; j < Tc; ++j) {
        float s = ck.x;
        #pragma unroll
        for (int o = 16; o > 0; o >>= 1) s += __shfl_xor_sync(0xffffffffu, s, o);
        if (n == 0) g_K[h][j] = 2.f * s;
        ck = cmul(ck, dtA);
    }
}

/* smem: u_s 8*2052 floats (65664B) + ws 2048 float2 (16384B) + Ks 32 floats (128B) */
#define SMEM_BYTES (HG * LPAD * 4 + NC * N2 * 8 + Tc * 4)

__global__ void __launch_bounds__(512, 2)
s4d_main(const float* __restrict__ u,
         const float* __restrict__ Dptr,
         float* __restrict__ out)
{
    extern __shared__ float sm[];
    float*  u_s = sm;                               /* [hh][l], stride LPAD  */
    float2* ws  = (float2*)(sm + HG * LPAD);        /* [chunk][mode]         */
    float*  Ks  = (float*)(ws + NC * N2);           /* 32 taps               */

    const int b    = blockIdx.y;
    const int h0   = blockIdx.x * HG;
    const int tid  = threadIdx.x;
    const int warp = tid >> 5;
    const int lane = tid & 31;
    const float Dv = *Dptr;

    /* ---- coalesced global load -> per-head contiguous smem ---- */
    const float* ub = u + (size_t)b * Lseq * Hdim + h0;
    for (int f = tid; f < Lseq * HG; f += 512) {
        int l = f >> 3, hh = f & 7;
        u_s[hh * LPAD + l] = ub[(size_t)l * Hdim + hh];
    }
    __syncthreads();

    for (int hh = 0; hh < HG; ++hh) {
        const int h = h0 + hh;
        const float* uh = u_s + hh * LPAD;

        if (tid < Tc) Ks[tid] = g_K[h][tid];   /* covered by the pass1 sync */

        /* ================= pass 1: chunk projections (lane = mode) =================
           w_c[n] = sum_t dtA^{31-t}*dtB * u[c*32+t], P generated by register recurrence */
        {
            float4 ab = g_AB[h][lane];
            const float axr = ab.x, axi = ab.y;
            float pr = ab.z, pi = ab.w;               /* p = dtB at t=31 */
            float w0r = 0, w0i = 0, w1r = 0, w1i = 0;
            float w2r = 0, w2i = 0, w3r = 0, w3i = 0;
            const float* b0 = uh + (warp     ) * Tc;
            const float* b1 = uh + (warp + 16) * Tc;
            const float* b2 = uh + (warp + 32) * Tc;
            const float* b3 = uh + (warp + 48) * Tc;

            #pragma unroll 2
            for (int tg = Tc - 4; tg >= 0; tg -= 4) {
                float4 a0 = *(const float4*)(b0 + tg);
                float4 a1 = *(const float4*)(b1 + tg);
                float4 a2 = *(const float4*)(b2 + tg);
                float4 a3 = *(const float4*)(b3 + tg);
                /* t = tg+3 */
                w0r = fmaf(pr, a0.w, w0r); w0i = fmaf(pi, a0.w, w0i);
                w1r = fmaf(pr, a1.w, w1r); w1i = fmaf(pi, a1.w, w1i);
                w2r = fmaf(pr, a2.w, w2r); w2i = fmaf(pi, a2.w, w2i);
                w3r = fmaf(pr, a3.w, w3r); w3i = fmaf(pi, a3.w, w3i);
                { float t_ = fmaf(pr, axr, -pi * axi); pi = fmaf(pr, axi, pi * axr); pr = t_; }
                /* t = tg+2 */
                w0r = fmaf(pr, a0.z, w0r); w0i = fmaf(pi, a0.z, w0i);
                w1r = fmaf(pr, a1.z, w1r); w1i = fmaf(pi, a1.z, w1i);
                w2r = fmaf(pr, a2.z, w2r); w2i = fmaf(pi, a2.z, w2i);
                w3r = fmaf(pr, a3.z, w3r); w3i = fmaf(pi, a3.z, w3i);
                { float t_ = fmaf(pr, axr, -pi * axi); pi = fmaf(pr, axi, pi * axr); pr = t_; }
                /* t = tg+1 */
                w0r = fmaf(pr, a0.y, w0r); w0i = fmaf(pi, a0.y, w0i);
                w1r = fmaf(pr, a1.y, w1r); w1i = fmaf(pi, a1.y, w1i);
                w2r = fmaf(pr, a2.y, w2r); w2i = fmaf(pi, a2.y, w2i);
                w3r = fmaf(pr, a3.y, w3r); w3i = fmaf(pi, a3.y, w3i);
                { float t_ = fmaf(pr, axr, -pi * axi); pi = fmaf(pr, axi, pi * axr); pr = t_; }
                /* t = tg */
                w0r = fmaf(pr, a0.x, w0r); w0i = fmaf(pi, a0.x, w0i);
                w1r = fmaf(pr, a1.x, w1r); w1i = fmaf(pi, a1.x, w1i);
                w2r = fmaf(pr, a2.x, w2r); w2i = fmaf(pi, a2.x, w2i);
                w3r = fmaf(pr, a3.x, w3r); w3i = fmaf(pi, a3.x, w3i);
                { float t_ = fmaf(pr, axr, -pi * axi); pi = fmaf(pr, axi, pi * axr); pr = t_; }
            }
            ws[(warp     ) * N2 + lane] = make_float2(w0r, w0i);
            ws[(warp + 16) * N2 + lane] = make_float2(w1r, w1i);
            ws[(warp + 32) * N2 + lane] = make_float2(w2r, w2i);
            ws[(warp + 48) * N2 + lane] = make_float2(w3r, w3i);
        }
        __syncthreads();

        /* ================= pass 2: serial chunk scan (warp 0, lane = mode) =========
           ws[c] := x' = 2*C*dtA * x_entry(c);  x <- AT*x + w_c                       */
        if (warp == 0) {
            float2 AT = g_AT[h][lane];
            float2 Q0 = g_Q0[h][lane];
            float xr = 0.f, xi = 0.f;
            #pragma unroll 4
            for (int c = 0; c < NC; ++c) {
                float2 w = ws[c * N2 + lane];
                ws[c * N2 + lane] = make_float2(fmaf(Q0.x, xr, -Q0.y * xi),
                                                fmaf(Q0.x, xi,  Q0.y * xr));
                float nr = fmaf(AT.x, xr, fmaf(-AT.y, xi, w.x));
                float ni = fmaf(AT.x, xi, fmaf( AT.y, xr, w.y));
                xr = nr; xi = ni;
            }
        }
        __syncthreads();

        /* ================= pass 3 (fused): corr + Toeplitz + D*u + GELU ============
           lane = (cl, tb): chunk = warp + 16*cl, outputs t = 4*tb .. 4*tb+3         */
        {
            const int cl = lane >> 3, tb = lane & 7, t0 = tb << 2;
            const int chunk = warp + 16 * cl;
            const float* uc = uh + chunk * Tc;

            float y0 = 0.f, y1 = 0.f, y2 = 0.f, y3 = 0.f;

            /* --- inter-chunk correction: y[t0+i] += Re( x'_n * dtA_n^{t0+i} ) --- */
            {
                const float4* Vr4 = (const float4*)&g_Vr [h][0][0];
                const float4* Vi4 = (const float4*)&g_Vin[h][0][0];
                const float4* xs4 = (const float4*)ws;
                const int xbase = chunk * (N2 / 2);
                #pragma unroll 4
                for (int n2 = 0; n2 < N2; n2 += 2) {
                    float4 x2  = xs4[xbase + (n2 >> 1)];      /* (xr0,xi0,xr1,xi1) */
                    float4 vr0 = Vr4[ n2      * 8 + tb];
                    float4 vi0 = Vi4[ n2      * 8 + tb];
                    float4 vr1 = Vr4[(n2 + 1) * 8 + tb];
                    float4 vi1 = Vi4[(n2 + 1) * 8 + tb];
                    y0 = fmaf(x2.x, vr0.x, y0); y0 = fmaf(x2.y, vi0.x, y0);
                    y1 = fmaf(x2.x, vr0.y, y1); y1 = fmaf(x2.y, vi0.y, y1);
                    y2 = fmaf(x2.x, vr0.z, y2); y2 = fmaf(x2.y, vi0.z, y2);
                    y3 = fmaf(x2.x, vr0.w, y3); y3 = fmaf(x2.y, vi0.w, y3);
                    y0 = fmaf(x2.z, vr1.x, y0); y0 = fmaf(x2.w, vi1.x, y0);
                    y1 = fmaf(x2.z, vr1.y, y1); y1 = fmaf(x2.w, vi1.y, y1);
                    y2 = fmaf(x2.z, vr1.z, y2); y2 = fmaf(x2.w, vi1.z, y2);
                    y3 = fmaf(x2.z, vr1.w, y3); y3 = fmaf(x2.w, vi1.w, y3);
                }
            }

            /* --- intra-chunk Toeplitz: sliding float4 window, 4 taps per group --- */
            float4 wc = *(const float4*)(uc + t0);   /* u[t0..t0+3] */
            const float4 uo = wc;
            const float4* Ks4 = (const float4*)Ks;
            #pragma unroll
            for (int jb = 0; jb < Tc; jb += 4) {
                const int idx = t0 - jb - 4;          /* both mult of 4 -> all-or-nothing */
                float4 wl;
                if (idx >= 0) wl = *(const float4*)(uc + idx);
                else          wl = make_float4(0.f, 0.f, 0.f, 0.f);
                float4 k4 = Ks4[jb >> 2];
                /* j = jb   : u[t0+i-jb]   = wc[i]                  */
                y0 = fmaf(k4.x, wc.x, y0); y1 = fmaf(k4.x, wc.y, y1);
                y2 = fmaf(k4.x, wc.z, y2); y3 = fmaf(k4.x, wc.w, y3);
                /* j = jb+1 : (wl.w, wc.x, wc.y, wc.z)              */
                y0 = fmaf(k4.y, wl.w, y0); y1 = fmaf(k4.y, wc.x, y1);
                y2 = fmaf(k4.y, wc.y, y2); y3 = fmaf(k4.y, wc.z, y3);
                /* j = jb+2 : (wl.z, wl.w, wc.x, wc.y)              */
                y0 = fmaf(k4.z, wl.z, y0); y1 = fmaf(k4.z, wl.w, y1);
                y2 = fmaf(k4.z, wc.x, y2); y3 = fmaf(k4.z, wc.y, y3);
                /* j = jb+3 : (wl.y, wl.z, wl.w, wc.x)              */
                y0 = fmaf(k4.w, wl.y, y0); y1 = fmaf(k4.w, wl.z, y1);
                y2 = fmaf(k4.w, wl.w, y2); y3 = fmaf(k4.w, wc.x, y3);
                wc = wl;
            }

            /* --- D*u + exact GELU, write back over u (own chunk only) --- */
            y0 = fmaf(Dv, uo.x, y0); y1 = fmaf(Dv, uo.y, y1);
            y2 = fmaf(Dv, uo.z, y2); y3 = fmaf(Dv, uo.w, y3);
            const float is2 = 0.70710678118654752440f;
            y0 = 0.5f * y0 * (1.f + erff(y0 * is2));
            y1 = 0.5f * y1 * (1.f + erff(y1 * is2));
            y2 = 0.5f * y2 * (1.f + erff(y2 * is2));
            y3 = 0.5f * y3 * (1.f + erff(y3 * is2));
            __syncwarp();   /* cross-lane u reads of this chunk complete before overwrite */
            *(float4*)(uh + chunk * Tc + t0) = make_float4(y0, y1, y2, y3);
        }
        __syncthreads();   /* ws + u region settled before next head */
    }

    /* ---- coalesced store ---- */
    float* ob = out + (size_t)b * Lseq * Hdim + h0;
    for (int f = tid; f < Lseq * HG; f += 512) {
        int l = f >> 3, hh = f & 7;
        ob[(size_t)l * Hdim + hh] = u_s[hh * LPAD + l];
    }
}

extern "C" void kernel_launch(void* const* d_in, const int* in_sizes, int n_in,
                              void* d_out, int out_size)
{
    const float* u      = (const float*)d_in[0];
    const float* log_dt = (const float*)d_in[1];
    const float* B_re   = (const float*)d_in[2];
    const float* B_im   = (const float*)d_in[3];
    const float* C      = (const float*)d_in[4];
    const float* A_real = (const float*)d_in[5];
    const float* A_imag = (const float*)d_in[6];
    const float* D      = (const float*)d_in[7];
    float* out = (float*)d_out;

    cudaFuncSetAttribute(s4d_main, cudaFuncAttributeMaxDynamicSharedMemorySize,
                         SMEM_BYTES);

    s4d_precompute<<<Hdim, N2>>>(log_dt, B_re, B_im, C, A_real, A_imag);

    dim3 grid(Hdim / HG, Bsz);
    s4d_main<<<grid, 512, SMEM_BYTES>>>(u, D, out);
}

// round 5
// speedup vs baseline: 1.1931x; 1.1371x over previous
#include <cuda_runtime.h>

#define Bsz   16
#define Lseq  2048
#define Hdim  512
#define N2    32
#define Tc    32
#define NC    (Lseq / Tc)   /* 64 chunks */
#define HG    8
#define LPAD  2052          /* per-head time-contiguous stride (mult of 4) */
#define NCW   8             /* chunks per warp within a stream */

/* ---- precomputed per-mode tables ---- */
__device__ float4 g_AB[Hdim][N2];        /* (dtA.re, dtA.im, dtB.re, dtB.im)      */
__device__ float2 g_Q0[Hdim][N2];        /* 2*C*dtA                               */
__device__ float2 g_AT[Hdim][N2];        /* dtA^32                                */
__device__ float2 g_AT8[Hdim][N2];       /* dtA^256 (8-chunk block aggregate)     */
__device__ float  g_Vr[Hdim][N2][Tc];    /* Re(dtA^t)                             */
__device__ float  g_Vin[Hdim][N2][Tc];   /* -Im(dtA^t)                            */
__device__ float  g_K[Hdim][Tc];         /* K[j] = 2*Re(sum_n C*dtB*dtA^j)        */

__device__ __forceinline__ float2 cmul(float2 a, float2 b) {
    return make_float2(fmaf(a.x, b.x, -a.y * b.y), fmaf(a.x, b.y, a.y * b.x));
}

__global__ void s4d_precompute(const float* __restrict__ log_dt,
                               const float* __restrict__ B_re,
                               const float* __restrict__ B_im,
                               const float* __restrict__ Cmat,
                               const float* __restrict__ A_real,
                               const float* __restrict__ A_imag)
{
    int h = blockIdx.x;
    int n = threadIdx.x;
    int idx = h * N2 + n;

    float dt  = expf(log_dt[h]);
    float Are = -expf(A_real[idx]) - 1e-6f;
    float Aim = A_imag[idx];

    float2 num = make_float2(1.f + 0.5f * dt * Are, 0.5f * dt * Aim);
    float2 den = make_float2(1.f + 1e-6f - 0.5f * dt * Are, -0.5f * dt * Aim);
    float  inv = 1.f / (den.x * den.x + den.y * den.y);
    float2 dtA = make_float2((num.x * den.x + num.y * den.y) * inv,
                             (num.y * den.x - num.x * den.y) * inv);
    float2 Bc  = make_float2(dt * B_re[idx], dt * B_im[idx]);
    float2 dtB = make_float2((Bc.x * den.x + Bc.y * den.y) * inv,
                             (Bc.y * den.x - Bc.x * den.y) * inv);
    float  Cv  = Cmat[idx];

    g_AB[h][n] = make_float4(dtA.x, dtA.y, dtB.x, dtB.y);
    g_Q0[h][n] = make_float2(2.f * Cv * dtA.x, 2.f * Cv * dtA.y);

    /* dtA^32 / dtA^256 by squaring */
    float2 a = dtA;
    #pragma unroll
    for (int s = 0; s < 5; ++s) a = cmul(a, a);
    g_AT[h][n] = a;
    float2 a8 = a;
    #pragma unroll
    for (int s = 0; s < 3; ++s) a8 = cmul(a8, a8);
    g_AT8[h][n] = a8;

    /* Vandermonde planes */
    float2 v = make_float2(1.f, 0.f);
    for (int t = 0; t < Tc; ++t) {
        g_Vr [h][n][t] =  v.x;
        g_Vin[h][n][t] = -v.y;
        v = cmul(v, dtA);
    }

    /* Toeplitz taps */
    float2 ck = make_float2(Cv * dtB.x, Cv * dtB.y);
    for (int j = 0; j < Tc; ++j) {
        float s = ck.x;
        #pragma unroll
        for (int o = 16; o > 0; o >>= 1) s += __shfl_xor_sync(0xffffffffu, s, o);
        if (n == 0) g_K[h][j] = 2.f * s;
        ck = cmul(ck, dtA);
    }
}

/* chunk projections for 4 chunks (bases b0..b3), lane = mode.
   w_c = sum_t dtA^{31-t} dtB * u[c*32+t]; P generated by register recurrence. */
__device__ __forceinline__ void proj4(const float* __restrict__ b0,
                                      const float* __restrict__ b1,
                                      const float* __restrict__ b2,
                                      const float* __restrict__ b3,
                                      float axr, float axi, float2 dtB,
                                      float2& o0, float2& o1, float2& o2, float2& o3)
{
    float pr = dtB.x, pi = dtB.y;
    float w0r = 0, w0i = 0, w1r = 0, w1i = 0;
    float w2r = 0, w2i = 0, w3r = 0, w3i = 0;
    #pragma unroll 2
    for (int tg = Tc - 4; tg >= 0; tg -= 4) {
        float4 a0 = *(const float4*)(b0 + tg);
        float4 a1 = *(const float4*)(b1 + tg);
        float4 a2 = *(const float4*)(b2 + tg);
        float4 a3 = *(const float4*)(b3 + tg);
        w0r = fmaf(pr, a0.w, w0r); w0i = fmaf(pi, a0.w, w0i);
        w1r = fmaf(pr, a1.w, w1r); w1i = fmaf(pi, a1.w, w1i);
        w2r = fmaf(pr, a2.w, w2r); w2i = fmaf(pi, a2.w, w2i);
        w3r = fmaf(pr, a3.w, w3r); w3i = fmaf(pi, a3.w, w3i);
        { float t_ = fmaf(pr, axr, -pi * axi); pi = fmaf(pr, axi, pi * axr); pr = t_; }
        w0r = fmaf(pr, a0.z, w0r); w0i = fmaf(pi, a0.z, w0i);
        w1r = fmaf(pr, a1.z, w1r); w1i = fmaf(pi, a1.z, w1i);
        w2r = fmaf(pr, a2.z, w2r); w2i = fmaf(pi, a2.z, w2i);
        w3r = fmaf(pr, a3.z, w3r); w3i = fmaf(pi, a3.z, w3i);
        { float t_ = fmaf(pr, axr, -pi * axi); pi = fmaf(pr, axi, pi * axr); pr = t_; }
        w0r = fmaf(pr, a0.y, w0r); w0i = fmaf(pi, a0.y, w0i);
        w1r = fmaf(pr, a1.y, w1r); w1i = fmaf(pi, a1.y, w1i);
        w2r = fmaf(pr, a2.y, w2r); w2i = fmaf(pi, a2.y, w2i);
        w3r = fmaf(pr, a3.y, w3r); w3i = fmaf(pi, a3.y, w3i);
        { float t_ = fmaf(pr, axr, -pi * axi); pi = fmaf(pr, axi, pi * axr); pr = t_; }
        w0r = fmaf(pr, a0.x, w0r); w0i = fmaf(pi, a0.x, w0i);
        w1r = fmaf(pr, a1.x, w1r); w1i = fmaf(pi, a1.x, w1i);
        w2r = fmaf(pr, a2.x, w2r); w2i = fmaf(pi, a2.x, w2i);
        w3r = fmaf(pr, a3.x, w3r); w3i = fmaf(pi, a3.x, w3i);
        { float t_ = fmaf(pr, axr, -pi * axi); pi = fmaf(pr, axi, pi * axr); pr = t_; }
    }
    o0 = make_float2(w0r, w0i); o1 = make_float2(w1r, w1i);
    o2 = make_float2(w2r, w2i); o3 = make_float2(w3r, w3i);
}

/* smem: u 65664B + ws 2 streams x 16KB + bs 4KB + Ks 256B */
#define SMEM_BYTES (HG * LPAD * 4 + 2 * NC * N2 * 8 + 2 * NCW * N2 * 8 + 2 * Tc * 4)

#define STREAM_BAR(id) asm volatile("bar.sync %0, 256;" :: "r"(id) : "memory")

__global__ void __launch_bounds__(512, 2)
s4d_main(const float* __restrict__ u,
         const float* __restrict__ Dptr,
         float* __restrict__ out)
{
    extern __shared__ float sm[];
    float*  u_s = sm;                                   /* [hh][l], stride LPAD */
    float2* ws  = (float2*)(sm + HG * LPAD);            /* [sid][chunk][mode] x' */
    float2* bs  = ws + 2 * NC * N2;                     /* [sid][wl][mode]       */
    float*  Ks2 = (float*)(bs + 2 * NCW * N2);          /* [sid][32]             */

    const int b    = blockIdx.y;
    const int h0   = blockIdx.x * HG;
    const int tid  = threadIdx.x;
    const int warp = tid >> 5;
    const int lane = tid & 31;
    const int sid  = warp >> 3;       /* stream 0/1 */
    const int wl   = warp & 7;        /* warp within stream */
    const int barid = 1 + sid;
    const float Dv = *Dptr;

    float2* wsS = ws + sid * (NC * N2);
    float2* bsS = bs + sid * (NCW * N2);
    float*  KsS = Ks2 + sid * Tc;

    /* ---- coalesced global load -> per-head contiguous smem ---- */
    const float* ub = u + (size_t)b * Lseq * Hdim + h0;
    for (int f = tid; f < Lseq * HG; f += 512) {
        int l = f >> 3, hh = f & 7;
        u_s[hh * LPAD + l] = ub[(size_t)l * Hdim + hh];
    }
    __syncthreads();

    for (int ih = 0; ih < 4; ++ih) {
        const int hh = 2 * ih + sid;
        const int h  = h0 + hh;
        const float* uh = u_s + hh * LPAD;

        if (wl == 0) KsS[lane] = g_K[h][lane];

        /* ===== pass 1: 8 chunk projections per warp, kept in registers ===== */
        float4 ab = g_AB[h][lane];
        float2 dtB = make_float2(ab.z, ab.w);
        float2 w0, w1, w2, w3, w4, w5, w6, w7;
        {
            const float* cb = uh + (NCW * wl) * Tc;
            proj4(cb,          cb + Tc,     cb + 2 * Tc, cb + 3 * Tc,
                  ab.x, ab.y, dtB, w0, w1, w2, w3);
            proj4(cb + 4 * Tc, cb + 5 * Tc, cb + 6 * Tc, cb + 7 * Tc,
                  ab.x, ab.y, dtB, w4, w5, w6, w7);
        }

        /* ===== scan step 1: block aggregate S = sum AT^{7-j} w_j (Horner) ===== */
        const float2 AT = g_AT[h][lane];
        {
            float sr = w0.x, si = w0.y;
            #define HSTEP(W) { float nr = fmaf(AT.x, sr, fmaf(-AT.y, si, (W).x)); \
                               float ni = fmaf(AT.x, si, fmaf( AT.y, sr, (W).y)); \
                               sr = nr; si = ni; }
            HSTEP(w1) HSTEP(w2) HSTEP(w3) HSTEP(w4) HSTEP(w5) HSTEP(w6) HSTEP(w7)
            #undef HSTEP
            bsS[wl * N2 + lane] = make_float2(sr, si);
        }
        STREAM_BAR(barid);

        /* ===== scan step 2: 8-entry scan of block aggregates (one warp) ===== */
        if (wl == 0) {
            float2 A8 = g_AT8[h][lane];
            float xr = 0.f, xi = 0.f;
            #pragma unroll
            for (int k = 0; k < NCW; ++k) {
                float2 S = bsS[k * N2 + lane];
                bsS[k * N2 + lane] = make_float2(xr, xi);
                float nr = fmaf(A8.x, xr, fmaf(-A8.y, xi, S.x));
                float ni = fmaf(A8.x, xi, fmaf( A8.y, xr, S.y));
                xr = nr; xi = ni;
            }
        }
        STREAM_BAR(barid);

        /* ===== scan step 3: expand within block; write x' = Q0 * x_entry ===== */
        {
            float2 Q0 = g_Q0[h][lane];
            float2 xv = bsS[wl * N2 + lane];
            float xr = xv.x, xi = xv.y;
            #define XSTEP(j, W) { \
                wsS[(NCW * wl + (j)) * N2 + lane] = \
                    make_float2(fmaf(Q0.x, xr, -Q0.y * xi), fmaf(Q0.x, xi, Q0.y * xr)); \
                float nr = fmaf(AT.x, xr, fmaf(-AT.y, xi, (W).x)); \
                float ni = fmaf(AT.x, xi, fmaf( AT.y, xr, (W).y)); \
                xr = nr; xi = ni; }
            XSTEP(0, w0) XSTEP(1, w1) XSTEP(2, w2) XSTEP(3, w3)
            XSTEP(4, w4) XSTEP(5, w5) XSTEP(6, w6) XSTEP(7, w7)
            #undef XSTEP
        }
        STREAM_BAR(barid);

        /* ===== pass 3: corr + Toeplitz + D*u + GELU, 8 chunks/warp in 2 reps ===== */
        const int cl = lane >> 3, tb = lane & 7, t0 = tb << 2;
        #pragma unroll
        for (int rep = 0; rep < 2; ++rep) {
            const int chunk = NCW * wl + 4 * rep + cl;
            const float* uc = uh + chunk * Tc;

            float y0 = 0.f, y1 = 0.f, y2 = 0.f, y3 = 0.f;

            /* inter-chunk correction via Vandermonde planes */
            {
                const float4* Vr4 = (const float4*)&g_Vr [h][0][0];
                const float4* Vi4 = (const float4*)&g_Vin[h][0][0];
                const float4* xs4 = (const float4*)wsS;
                const int xbase = chunk * (N2 / 2);
                #pragma unroll 4
                for (int n2 = 0; n2 < N2; n2 += 2) {
                    float4 x2  = xs4[xbase + (n2 >> 1)];
                    float4 vr0 = Vr4[ n2      * 8 + tb];
                    float4 vi0 = Vi4[ n2      * 8 + tb];
                    float4 vr1 = Vr4[(n2 + 1) * 8 + tb];
                    float4 vi1 = Vi4[(n2 + 1) * 8 + tb];
                    y0 = fmaf(x2.x, vr0.x, y0); y0 = fmaf(x2.y, vi0.x, y0);
                    y1 = fmaf(x2.x, vr0.y, y1); y1 = fmaf(x2.y, vi0.y, y1);
                    y2 = fmaf(x2.x, vr0.z, y2); y2 = fmaf(x2.y, vi0.z, y2);
                    y3 = fmaf(x2.x, vr0.w, y3); y3 = fmaf(x2.y, vi0.w, y3);
                    y0 = fmaf(x2.z, vr1.x, y0); y0 = fmaf(x2.w, vi1.x, y0);
                    y1 = fmaf(x2.z, vr1.y, y1); y1 = fmaf(x2.w, vi1.y, y1);
                    y2 = fmaf(x2.z, vr1.z, y2); y2 = fmaf(x2.w, vi1.z, y2);
                    y3 = fmaf(x2.z, vr1.w, y3); y3 = fmaf(x2.w, vi1.w, y3);
                }
            }

            /* intra-chunk Toeplitz: sliding float4 window */
            float4 wc = *(const float4*)(uc + t0);
            const float4 uo = wc;
            const float4* Ks4 = (const float4*)KsS;
            #pragma unroll
            for (int jb = 0; jb < Tc; jb += 4) {
                const int idx = t0 - jb - 4;
                float4 wlq;
                if (idx >= 0) wlq = *(const float4*)(uc + idx);
                else          wlq = make_float4(0.f, 0.f, 0.f, 0.f);
                float4 k4 = Ks4[jb >> 2];
                y0 = fmaf(k4.x, wc.x, y0); y1 = fmaf(k4.x, wc.y, y1);
                y2 = fmaf(k4.x, wc.z, y2); y3 = fmaf(k4.x, wc.w, y3);
                y0 = fmaf(k4.y, wlq.w, y0); y1 = fmaf(k4.y, wc.x, y1);
                y2 = fmaf(k4.y, wc.y, y2); y3 = fmaf(k4.y, wc.z, y3);
                y0 = fmaf(k4.z, wlq.z, y0); y1 = fmaf(k4.z, wlq.w, y1);
                y2 = fmaf(k4.z, wc.x, y2); y3 = fmaf(k4.z, wc.y, y3);
                y0 = fmaf(k4.w, wlq.y, y0); y1 = fmaf(k4.w, wlq.z, y1);
                y2 = fmaf(k4.w, wlq.w, y2); y3 = fmaf(k4.w, wc.x, y3);
                wc = wlq;
            }

            /* + D*u, exact GELU, write back over u */
            y0 = fmaf(Dv, uo.x, y0); y1 = fmaf(Dv, uo.y, y1);
            y2 = fmaf(Dv, uo.z, y2); y3 = fmaf(Dv, uo.w, y3);
            const float is2 = 0.70710678118654752440f;
            y0 = 0.5f * y0 * (1.f + erff(y0 * is2));
            y1 = 0.5f * y1 * (1.f + erff(y1 * is2));
            y2 = 0.5f * y2 * (1.f + erff(y2 * is2));
            y3 = 0.5f * y3 * (1.f + erff(y3 * is2));
            __syncwarp();   /* cross-lane reads of this chunk group done */
            *(float4*)(uh + chunk * Tc + t0) = make_float4(y0, y1, y2, y3);
        }
        STREAM_BAR(barid);   /* ws/bs/Ks settled before next head */
    }
    __syncthreads();

    /* ---- coalesced store ---- */
    float* ob = out + (size_t)b * Lseq * Hdim + h0;
    for (int f = tid; f < Lseq * HG; f += 512) {
        int l = f >> 3, hh = f & 7;
        ob[(size_t)l * Hdim + hh] = u_s[hh * LPAD + l];
    }
}

extern "C" void kernel_launch(void* const* d_in, const int* in_sizes, int n_in,
                              void* d_out, int out_size)
{
    const float* u      = (const float*)d_in[0];
    const float* log_dt = (const float*)d_in[1];
    const float* B_re   = (const float*)d_in[2];
    const float* B_im   = (const float*)d_in[3];
    const float* C      = (const float*)d_in[4];
    const float* A_real = (const float*)d_in[5];
    const float* A_imag = (const float*)d_in[6];
    const float* D      = (const float*)d_in[7];
    float* out = (float*)d_out;

    cudaFuncSetAttribute(s4d_main, cudaFuncAttributeMaxDynamicSharedMemorySize,
                         SMEM_BYTES);

    s4d_precompute<<<Hdim, N2>>>(log_dt, B_re, B_im, C, A_real, A_imag);

    dim3 grid(Hdim / HG, Bsz);
    s4d_main<<<grid, 512, SMEM_BYTES>>>(u, D, out);
}

// round 6
// speedup vs baseline: 1.4782x; 1.2390x over previous
#include <cuda_runtime.h>

#define Bsz   16
#define Lseq  2048
#define Hdim  512
#define N2    32
#define Tc    32
#define NC    (Lseq / Tc)   /* 64 chunks */
#define HG    8
#define LPAD  2052          /* per-head time-contiguous stride (mult of 4) */
#define NCW   8             /* chunks per warp within a stream */

/* ---- precomputed per-mode tables ---- */
__device__ float4 g_AB[Hdim][N2];        /* (dtA.re, dtA.im, dtB.re, dtB.im)      */
__device__ float2 g_Q0[Hdim][N2];        /* 2*C*dtA                               */
__device__ float2 g_AT[Hdim][N2];        /* dtA^32                                */
__device__ float2 g_AT8[Hdim][N2];       /* dtA^256 (8-chunk block aggregate)     */
__device__ float  g_Vr[Hdim][N2][Tc];    /* Re(dtA^t)                             */
__device__ float  g_Vin[Hdim][N2][Tc];   /* -Im(dtA^t)                            */
__device__ float  g_K[Hdim][Tc];         /* K[j] = 2*Re(sum_n C*dtB*dtA^j)        */

__device__ __forceinline__ float2 cmul(float2 a, float2 b) {
    return make_float2(fmaf(a.x, b.x, -a.y * b.y), fmaf(a.x, b.y, a.y * b.x));
}

__global__ void s4d_precompute(const float* __restrict__ log_dt,
                               const float* __restrict__ B_re,
                               const float* __restrict__ B_im,
                               const float* __restrict__ Cmat,
                               const float* __restrict__ A_real,
                               const float* __restrict__ A_imag)
{
    int h = blockIdx.x;
    int n = threadIdx.x;
    int idx = h * N2 + n;

    float dt  = expf(log_dt[h]);
    float Are = -expf(A_real[idx]) - 1e-6f;
    float Aim = A_imag[idx];

    float2 num = make_float2(1.f + 0.5f * dt * Are, 0.5f * dt * Aim);
    float2 den = make_float2(1.f + 1e-6f - 0.5f * dt * Are, -0.5f * dt * Aim);
    float  inv = 1.f / (den.x * den.x + den.y * den.y);
    float2 dtA = make_float2((num.x * den.x + num.y * den.y) * inv,
                             (num.y * den.x - num.x * den.y) * inv);
    float2 Bc  = make_float2(dt * B_re[idx], dt * B_im[idx]);
    float2 dtB = make_float2((Bc.x * den.x + Bc.y * den.y) * inv,
                             (Bc.y * den.x - Bc.x * den.y) * inv);
    float  Cv  = Cmat[idx];

    g_AB[h][n] = make_float4(dtA.x, dtA.y, dtB.x, dtB.y);
    g_Q0[h][n] = make_float2(2.f * Cv * dtA.x, 2.f * Cv * dtA.y);

    /* dtA^32 / dtA^256 by squaring */
    float2 a = dtA;
    #pragma unroll
    for (int s = 0; s < 5; ++s) a = cmul(a, a);
    g_AT[h][n] = a;
    float2 a8 = a;
    #pragma unroll
    for (int s = 0; s < 3; ++s) a8 = cmul(a8, a8);
    g_AT8[h][n] = a8;

    /* Vandermonde planes */
    float2 v = make_float2(1.f, 0.f);
    for (int t = 0; t < Tc; ++t) {
        g_Vr [h][n][t] =  v.x;
        g_Vin[h][n][t] = -v.y;
        v = cmul(v, dtA);
    }

    /* Toeplitz taps */
    float2 ck = make_float2(Cv * dtB.x, Cv * dtB.y);
    for (int j = 0; j < Tc; ++j) {
        float s = ck.x;
        #pragma unroll
        for (int o = 16; o > 0; o >>= 1) s += __shfl_xor_sync(0xffffffffu, s, o);
        if (n == 0) g_K[h][j] = 2.f * s;
        ck = cmul(ck, dtA);
    }
}

/* chunk projections for 4 chunks (bases b0..b3), lane = mode. */
__device__ __forceinline__ void proj4(const float* __restrict__ b0,
                                      const float* __restrict__ b1,
                                      const float* __restrict__ b2,
                                      const float* __restrict__ b3,
                                      float axr, float axi, float2 dtB,
                                      float2& o0, float2& o1, float2& o2, float2& o3)
{
    float pr = dtB.x, pi = dtB.y;
    float w0r = 0, w0i = 0, w1r = 0, w1i = 0;
    float w2r = 0, w2i = 0, w3r = 0, w3i = 0;
    #pragma unroll 2
    for (int tg = Tc - 4; tg >= 0; tg -= 4) {
        float4 a0 = *(const float4*)(b0 + tg);
        float4 a1 = *(const float4*)(b1 + tg);
        float4 a2 = *(const float4*)(b2 + tg);
        float4 a3 = *(const float4*)(b3 + tg);
        w0r = fmaf(pr, a0.w, w0r); w0i = fmaf(pi, a0.w, w0i);
        w1r = fmaf(pr, a1.w, w1r); w1i = fmaf(pi, a1.w, w1i);
        w2r = fmaf(pr, a2.w, w2r); w2i = fmaf(pi, a2.w, w2i);
        w3r = fmaf(pr, a3.w, w3r); w3i = fmaf(pi, a3.w, w3i);
        { float t_ = fmaf(pr, axr, -pi * axi); pi = fmaf(pr, axi, pi * axr); pr = t_; }
        w0r = fmaf(pr, a0.z, w0r); w0i = fmaf(pi, a0.z, w0i);
        w1r = fmaf(pr, a1.z, w1r); w1i = fmaf(pi, a1.z, w1i);
        w2r = fmaf(pr, a2.z, w2r); w2i = fmaf(pi, a2.z, w2i);
        w3r = fmaf(pr, a3.z, w3r); w3i = fmaf(pi, a3.z, w3i);
        { float t_ = fmaf(pr, axr, -pi * axi); pi = fmaf(pr, axi, pi * axr); pr = t_; }
        w0r = fmaf(pr, a0.y, w0r); w0i = fmaf(pi, a0.y, w0i);
        w1r = fmaf(pr, a1.y, w1r); w1i = fmaf(pi, a1.y, w1i);
        w2r = fmaf(pr, a2.y, w2r); w2i = fmaf(pi, a2.y, w2i);
        w3r = fmaf(pr, a3.y, w3r); w3i = fmaf(pi, a3.y, w3i);
        { float t_ = fmaf(pr, axr, -pi * axi); pi = fmaf(pr, axi, pi * axr); pr = t_; }
        w0r = fmaf(pr, a0.x, w0r); w0i = fmaf(pi, a0.x, w0i);
        w1r = fmaf(pr, a1.x, w1r); w1i = fmaf(pi, a1.x, w1i);
        w2r = fmaf(pr, a2.x, w2r); w2i = fmaf(pi, a2.x, w2i);
        w3r = fmaf(pr, a3.x, w3r); w3i = fmaf(pi, a3.x, w3i);
        { float t_ = fmaf(pr, axr, -pi * axi); pi = fmaf(pr, axi, pi * axr); pr = t_; }
    }
    o0 = make_float2(w0r, w0i); o1 = make_float2(w1r, w1i);
    o2 = make_float2(w2r, w2i); o3 = make_float2(w3r, w3i);
}

/* smem: u 65664B + ws 2 streams x 16KB + bs 4KB + Ks 256B */
#define SMEM_BYTES (HG * LPAD * 4 + 2 * NC * N2 * 8 + 2 * NCW * N2 * 8 + 2 * Tc * 4)

#define STREAM_BAR(id) asm volatile("bar.sync %0, 256;" :: "r"(id) : "memory")

__global__ void __launch_bounds__(512, 2)
s4d_main(const float* __restrict__ u,
         const float* __restrict__ Dptr,
         float* __restrict__ out)
{
    extern __shared__ float sm[];
    float*  u_s = sm;                                   /* [hh][l], stride LPAD */
    float2* ws  = (float2*)(sm + HG * LPAD);            /* [sid][chunk][mode] x' */
    float2* bs  = ws + 2 * NC * N2;                     /* [sid][wl][mode]       */
    float*  Ks2 = (float*)(bs + 2 * NCW * N2);          /* [sid][32]             */

    const int b    = blockIdx.y;
    const int h0   = blockIdx.x * HG;
    const int tid  = threadIdx.x;
    const int warp = tid >> 5;
    const int lane = tid & 31;
    const int sid  = warp >> 3;       /* stream 0/1 */
    const int wl   = warp & 7;        /* warp within stream */
    const int barid = 1 + sid;
    const float Dv = *Dptr;

    float2* wsS = ws + sid * (NC * N2);
    float2* bsS = bs + sid * (NCW * N2);
    float*  KsS = Ks2 + sid * Tc;

    /* ---- coalesced global load -> per-head contiguous smem ---- */
    const float* ub = u + (size_t)b * Lseq * Hdim + h0;
    for (int f = tid; f < Lseq * HG; f += 512) {
        int l = f >> 3, hh = f & 7;
        u_s[hh * LPAD + l] = ub[(size_t)l * Hdim + hh];
    }
    __syncthreads();

    for (int ih = 0; ih < 4; ++ih) {
        const int hh = 2 * ih + sid;
        const int h  = h0 + hh;
        const float* uh = u_s + hh * LPAD;

        if (wl == 0) KsS[lane] = g_K[h][lane];

        /* ===== pass 1: 8 chunk projections per warp, kept in registers ===== */
        float4 ab = g_AB[h][lane];
        float2 dtB = make_float2(ab.z, ab.w);
        float2 w0, w1, w2, w3, w4, w5, w6, w7;
        {
            const float* cb = uh + (NCW * wl) * Tc;
            proj4(cb,          cb + Tc,     cb + 2 * Tc, cb + 3 * Tc,
                  ab.x, ab.y, dtB, w0, w1, w2, w3);
            proj4(cb + 4 * Tc, cb + 5 * Tc, cb + 6 * Tc, cb + 7 * Tc,
                  ab.x, ab.y, dtB, w4, w5, w6, w7);
        }

        /* ===== scan step 1: block aggregate S = sum AT^{7-j} w_j (Horner) ===== */
        const float2 AT = g_AT[h][lane];
        {
            float sr = w0.x, si = w0.y;
            #define HSTEP(W) { float nr = fmaf(AT.x, sr, fmaf(-AT.y, si, (W).x)); \
                               float ni = fmaf(AT.x, si, fmaf( AT.y, sr, (W).y)); \
                               sr = nr; si = ni; }
            HSTEP(w1) HSTEP(w2) HSTEP(w3) HSTEP(w4) HSTEP(w5) HSTEP(w6) HSTEP(w7)
            #undef HSTEP
            bsS[wl * N2 + lane] = make_float2(sr, si);
        }
        STREAM_BAR(barid);

        /* ===== scan step 2: 8-entry scan of block aggregates (one warp) ===== */
        if (wl == 0) {
            float2 A8 = g_AT8[h][lane];
            float xr = 0.f, xi = 0.f;
            #pragma unroll
            for (int k = 0; k < NCW; ++k) {
                float2 S = bsS[k * N2 + lane];
                bsS[k * N2 + lane] = make_float2(xr, xi);
                float nr = fmaf(A8.x, xr, fmaf(-A8.y, xi, S.x));
                float ni = fmaf(A8.x, xi, fmaf( A8.y, xr, S.y));
                xr = nr; xi = ni;
            }
        }
        STREAM_BAR(barid);

        /* ===== scan step 3: expand within block; write x' = Q0 * x_entry ===== */
        {
            float2 Q0 = g_Q0[h][lane];
            float2 xv = bsS[wl * N2 + lane];
            float xr = xv.x, xi = xv.y;
            #define XSTEP(j, W) { \
                wsS[(NCW * wl + (j)) * N2 + lane] = \
                    make_float2(fmaf(Q0.x, xr, -Q0.y * xi), fmaf(Q0.x, xi, Q0.y * xr)); \
                float nr = fmaf(AT.x, xr, fmaf(-AT.y, xi, (W).x)); \
                float ni = fmaf(AT.x, xi, fmaf( AT.y, xr, (W).y)); \
                xr = nr; xi = ni; }
            XSTEP(0, w0) XSTEP(1, w1) XSTEP(2, w2) XSTEP(3, w3)
            XSTEP(4, w4) XSTEP(5, w5) XSTEP(6, w6) XSTEP(7, w7)
            #undef XSTEP
        }
        STREAM_BAR(barid);

        /* ===== pass 3: corr (V loaded ONCE per warp, 8 chunk accumulators) +
                 Toeplitz + D*u + GELU.  lane = (cl, tb); chunks A = 8wl+cl,
                 B = 8wl+4+cl                                                  ===== */
        {
            const int cl = lane >> 3, tb = lane & 7, t0 = tb << 2;
            const int chunkA = NCW * wl + cl;
            const int chunkB = NCW * wl + 4 + cl;

            float yA0 = 0.f, yA1 = 0.f, yA2 = 0.f, yA3 = 0.f;
            float yB0 = 0.f, yB1 = 0.f, yB2 = 0.f, yB3 = 0.f;

            /* --- inter-chunk correction, rep-merged: each V load feeds 8 acc --- */
            {
                const float4* Vr4 = (const float4*)&g_Vr [h][0][0];
                const float4* Vi4 = (const float4*)&g_Vin[h][0][0];
                const float4* xs4 = (const float4*)wsS;
                const int xbA = chunkA * (N2 / 2);
                const int xbB = chunkB * (N2 / 2);
                #pragma unroll 4
                for (int n2 = 0; n2 < N2; n2 += 2) {
                    float4 vr0 = Vr4[ n2      * 8 + tb];
                    float4 vi0 = Vi4[ n2      * 8 + tb];
                    float4 vr1 = Vr4[(n2 + 1) * 8 + tb];
                    float4 vi1 = Vi4[(n2 + 1) * 8 + tb];
                    float4 xa  = xs4[xbA + (n2 >> 1)];
                    float4 xb  = xs4[xbB + (n2 >> 1)];

                    yA0 = fmaf(xa.x, vr0.x, yA0); yA0 = fmaf(xa.y, vi0.x, yA0);
                    yA1 = fmaf(xa.x, vr0.y, yA1); yA1 = fmaf(xa.y, vi0.y, yA1);
                    yA2 = fmaf(xa.x, vr0.z, yA2); yA2 = fmaf(xa.y, vi0.z, yA2);
                    yA3 = fmaf(xa.x, vr0.w, yA3); yA3 = fmaf(xa.y, vi0.w, yA3);
                    yA0 = fmaf(xa.z, vr1.x, yA0); yA0 = fmaf(xa.w, vi1.x, yA0);
                    yA1 = fmaf(xa.z, vr1.y, yA1); yA1 = fmaf(xa.w, vi1.y, yA1);
                    yA2 = fmaf(xa.z, vr1.z, yA2); yA2 = fmaf(xa.w, vi1.z, yA2);
                    yA3 = fmaf(xa.z, vr1.w, yA3); yA3 = fmaf(xa.w, vi1.w, yA3);

                    yB0 = fmaf(xb.x, vr0.x, yB0); yB0 = fmaf(xb.y, vi0.x, yB0);
                    yB1 = fmaf(xb.x, vr0.y, yB1); yB1 = fmaf(xb.y, vi0.y, yB1);
                    yB2 = fmaf(xb.x, vr0.z, yB2); yB2 = fmaf(xb.y, vi0.z, yB2);
                    yB3 = fmaf(xb.x, vr0.w, yB3); yB3 = fmaf(xb.y, vi0.w, yB3);
                    yB0 = fmaf(xb.z, vr1.x, yB0); yB0 = fmaf(xb.w, vi1.x, yB0);
                    yB1 = fmaf(xb.z, vr1.y, yB1); yB1 = fmaf(xb.w, vi1.y, yB1);
                    yB2 = fmaf(xb.z, vr1.z, yB2); yB2 = fmaf(xb.w, vi1.z, yB2);
                    yB3 = fmaf(xb.z, vr1.w, yB3); yB3 = fmaf(xb.w, vi1.w, yB3);
                }
            }

            /* --- intra-chunk Toeplitz + epilogue, per rep (sequential) --- */
            const float4* Ks4 = (const float4*)KsS;
            const float is2 = 0.70710678118654752440f;

            #pragma unroll
            for (int rep = 0; rep < 2; ++rep) {
                const int chunk = (rep == 0) ? chunkA : chunkB;
                const float* uc = uh + chunk * Tc;
                float y0 = (rep == 0) ? yA0 : yB0;
                float y1 = (rep == 0) ? yA1 : yB1;
                float y2 = (rep == 0) ? yA2 : yB2;
                float y3 = (rep == 0) ? yA3 : yB3;

                float4 wc = *(const float4*)(uc + t0);
                const float4 uo = wc;
                #pragma unroll
                for (int jb = 0; jb < Tc; jb += 4) {
                    const int idx = t0 - jb - 4;
                    float4 wlq;
                    if (idx >= 0) wlq = *(const float4*)(uc + idx);
                    else          wlq = make_float4(0.f, 0.f, 0.f, 0.f);
                    float4 k4 = Ks4[jb >> 2];
                    y0 = fmaf(k4.x, wc.x, y0); y1 = fmaf(k4.x, wc.y, y1);
                    y2 = fmaf(k4.x, wc.z, y2); y3 = fmaf(k4.x, wc.w, y3);
                    y0 = fmaf(k4.y, wlq.w, y0); y1 = fmaf(k4.y, wc.x, y1);
                    y2 = fmaf(k4.y, wc.y, y2); y3 = fmaf(k4.y, wc.z, y3);
                    y0 = fmaf(k4.z, wlq.z, y0); y1 = fmaf(k4.z, wlq.w, y1);
                    y2 = fmaf(k4.z, wc.x, y2); y3 = fmaf(k4.z, wc.y, y3);
                    y0 = fmaf(k4.w, wlq.y, y0); y1 = fmaf(k4.w, wlq.z, y1);
                    y2 = fmaf(k4.w, wlq.w, y2); y3 = fmaf(k4.w, wc.x, y3);
                    wc = wlq;
                }

                y0 = fmaf(Dv, uo.x, y0); y1 = fmaf(Dv, uo.y, y1);
                y2 = fmaf(Dv, uo.z, y2); y3 = fmaf(Dv, uo.w, y3);
                y0 = 0.5f * y0 * (1.f + erff(y0 * is2));
                y1 = 0.5f * y1 * (1.f + erff(y1 * is2));
                y2 = 0.5f * y2 * (1.f + erff(y2 * is2));
                y3 = 0.5f * y3 * (1.f + erff(y3 * is2));
                if (rep == 0) { yA0 = y0; yA1 = y1; yA2 = y2; yA3 = y3; }
                else          { yB0 = y0; yB1 = y1; yB2 = y2; yB3 = y3; }
            }

            /* all u reads of both chunks complete before overwrite */
            __syncwarp();
            *(float4*)(uh + chunkA * Tc + t0) = make_float4(yA0, yA1, yA2, yA3);
            *(float4*)(uh + chunkB * Tc + t0) = make_float4(yB0, yB1, yB2, yB3);
        }
        STREAM_BAR(barid);   /* ws/bs/Ks settled before next head */
    }
    __syncthreads();

    /* ---- coalesced store ---- */
    float* ob = out + (size_t)b * Lseq * Hdim + h0;
    for (int f = tid; f < Lseq * HG; f += 512) {
        int l = f >> 3, hh = f & 7;
        ob[(size_t)l * Hdim + hh] = u_s[hh * LPAD + l];
    }
}

extern "C" void kernel_launch(void* const* d_in, const int* in_sizes, int n_in,
                              void* d_out, int out_size)
{
    const float* u      = (const float*)d_in[0];
    const float* log_dt = (const float*)d_in[1];
    const float* B_re   = (const float*)d_in[2];
    const float* B_im   = (const float*)d_in[3];
    const float* C      = (const float*)d_in[4];
    const float* A_real = (const float*)d_in[5];
    const float* A_imag = (const float*)d_in[6];
    const float* D      = (const float*)d_in[7];
    float* out = (float*)d_out;

    cudaFuncSetAttribute(s4d_main, cudaFuncAttributeMaxDynamicSharedMemorySize,
                         SMEM_BYTES);

    s4d_precompute<<<Hdim, N2>>>(log_dt, B_re, B_im, C, A_real, A_imag);

    dim3 grid(Hdim / HG, Bsz);
    s4d_main<<<grid, 512, SMEM_BYTES>>>(u, D, out);
}